// round 8
// baseline (speedup 1.0000x reference)
#include <cuda_runtime.h>
#include <cuda_bf16.h>
#include <cstdint>

#define K_DIM 2048
#define INV_F (1.0f / 2048.0f)
#define M_TOTAL 16384
#define N_PAD 1024
#define BM 128
#define BN 128
#define BK 64                               // bf16 per stage (128 bytes/row)
#define STAGES 3
#define SA_BYTES 144                        // 128B data + 16B pad: conflict-free
#define A_TILE_BYTES (BM * SA_BYTES)        // 18432
#define STAGE_BYTES (2 * A_TILE_BYTES)      // 36864
#define DYN_SMEM (STAGES * STAGE_BYTES)     // 110592  (2 CTAs/SM)

// Scratch (no device allocation allowed): bf16 operands + exact fp32 norms.
__device__ __align__(16) __nv_bfloat16 g_xb[(size_t)M_TOTAL * K_DIM];
__device__ __align__(16) __nv_bfloat16 g_wb[(size_t)N_PAD * K_DIM];
__device__ float g_x2[M_TOTAL];
__device__ float g_w2[N_PAD];

__device__ __forceinline__ uint32_t smem_u32(const void* p) {
    return (uint32_t)__cvta_generic_to_shared(p);
}

__device__ __forceinline__ void ldm_x4(uint32_t* r, uint32_t addr) {
    asm volatile("ldmatrix.sync.aligned.m8n8.x4.shared.b16 {%0,%1,%2,%3}, [%4];"
                 : "=r"(r[0]), "=r"(r[1]), "=r"(r[2]), "=r"(r[3]) : "r"(addr));
}

__device__ __forceinline__ void mma_bf16(float* d, const uint32_t* a, const uint32_t* b) {
    asm volatile(
        "mma.sync.aligned.m16n8k16.row.col.f32.bf16.bf16.f32 "
        "{%0,%1,%2,%3}, {%4,%5,%6,%7}, {%8,%9}, {%0,%1,%2,%3};"
        : "+f"(d[0]), "+f"(d[1]), "+f"(d[2]), "+f"(d[3])
        : "r"(a[0]), "r"(a[1]), "r"(a[2]), "r"(a[3]), "r"(b[0]), "r"(b[1]));
}

// ---------------- fused fp32->bf16 convert + exact fp32 row sum-of-squares ----------------

__global__ void __launch_bounds__(256) convert_kernel(const float* __restrict__ x,
                                                      const float* __restrict__ w,
                                                      int M, int N) {
    int b = blockIdx.x;
    const float4* src;
    uint2* dst;
    float* norm;
    if (b < M) {
        src = reinterpret_cast<const float4*>(x + (size_t)b * K_DIM);
        dst = reinterpret_cast<uint2*>(g_xb + (size_t)b * K_DIM);
        norm = &g_x2[b];
    } else {
        int row = b - M;
        dst = reinterpret_cast<uint2*>(g_wb + (size_t)row * K_DIM);
        if (row >= N) {
#pragma unroll
            for (int i = 0; i < 2; ++i) dst[threadIdx.x + i * 256] = make_uint2(0u, 0u);
            if (threadIdx.x == 0) g_w2[row] = 0.f;
            return;
        }
        src = reinterpret_cast<const float4*>(w + (size_t)row * K_DIM);
        norm = &g_w2[row];
    }
    float s = 0.f;
#pragma unroll
    for (int i = 0; i < 2; ++i) {
        int idx = threadIdx.x + i * 256;
        float4 v = src[idx];
        s += v.x * v.x + v.y * v.y + v.z * v.z + v.w * v.w;
        __nv_bfloat162 p0 = __float22bfloat162_rn(make_float2(v.x, v.y));
        __nv_bfloat162 p1 = __float22bfloat162_rn(make_float2(v.z, v.w));
        uint2 o;
        o.x = *reinterpret_cast<uint32_t*>(&p0);
        o.y = *reinterpret_cast<uint32_t*>(&p1);
        dst[idx] = o;
    }
#pragma unroll
    for (int o = 16; o > 0; o >>= 1) s += __shfl_xor_sync(0xffffffffu, s, o);
    __shared__ float red[8];
    if ((threadIdx.x & 31) == 0) red[threadIdx.x >> 5] = s;
    __syncthreads();
    if (threadIdx.x == 0) {
        float t = 0.f;
#pragma unroll
        for (int i = 0; i < 8; ++i) t += red[i];
        *norm = t;
    }
}

// ---------------- bf16 mma.sync GEMM: CTA 128x128, 4 warps of 64x64, pipelined frags ----------------

__device__ __forceinline__ void load_stage(uint32_t base, int s, int kt,
                                           int m0, int n0, int tid) {
    uint32_t sb = base + (uint32_t)s * STAGE_BYTES;
    const __nv_bfloat16* xa = g_xb + (size_t)m0 * K_DIM + kt * BK;
    const __nv_bfloat16* wb = g_wb + (size_t)n0 * K_DIM + kt * BK;
    // A: 128 rows x 8 chunks = 1024; B same; total 2048 -> 16 per thread (128 threads).
#pragma unroll
    for (int i = 0; i < 16; ++i) {
        int idx = tid + i * 128;                 // 0..2047
        int op = idx >> 10;                      // 0 = A, 1 = B
        int r = (idx >> 3) & 127;
        int c = idx & 7;
        uint32_t dst = sb + (uint32_t)op * A_TILE_BYTES + (uint32_t)(r * SA_BYTES + c * 16);
        const __nv_bfloat16* src = (op ? wb : xa) + (size_t)r * K_DIM + c * 8;
        asm volatile("cp.async.cg.shared.global [%0], [%1], 16;"
                     :: "r"(dst), "l"(src) : "memory");
    }
    asm volatile("cp.async.commit_group;" ::: "memory");
}

__global__ void __launch_bounds__(128, 2) gemm_mma_kernel(float* __restrict__ out, int N) {
    extern __shared__ __align__(16) char dyn_smem[];
    __shared__ float s_x2[BM];
    __shared__ float s_w2[BN];

    const uint32_t base = smem_u32(dyn_smem);
    const int tid = threadIdx.x;
    const int wid = tid >> 5, lid = tid & 31;
    const int mw = (wid >> 1) * 64;    // warp M offset (2 in M)
    const int nw = (wid & 1) * 64;     // warp N offset (2 in N)
    const int m0 = blockIdx.y * BM;
    const int n0 = blockIdx.x * BN;

    const uint32_t a_lane = (uint32_t)((mw + (lid & 15)) * SA_BYTES + (lid >> 4) * 16);
    const uint32_t b_lane = (uint32_t)A_TILE_BYTES +
        (uint32_t)((nw + (lid & 7) + ((lid >> 4) << 3)) * SA_BYTES + ((lid >> 3) & 1) * 16);

    s_x2[tid] = g_x2[m0 + tid];
    s_w2[tid] = g_w2[n0 + tid];

    // Prologue: prefetch STAGES-1 stages.
#pragma unroll
    for (int s = 0; s < STAGES - 1; ++s) load_stage(base, s, s, m0, n0, tid);

    float acc[4][8][4] = {};
    uint32_t a_buf[2][4][4], b_buf[2][4][4];

    const int NITER = K_DIM / BK;  // 32
    for (int kt = 0; kt < NITER; ++kt) {
        asm volatile("cp.async.wait_group %0;" :: "n"(STAGES - 2) : "memory");
        __syncthreads();

        // Hoist next-stage gmem prefetch so L2 latency overlaps this kt's compute.
        int kl = kt + STAGES - 1;
        if (kl < NITER) load_stage(base, kl % STAGES, kl, m0, n0, tid);
        else asm volatile("cp.async.commit_group;" ::: "memory");

        uint32_t sb = base + (uint32_t)(kt % STAGES) * STAGE_BYTES;
        const uint32_t al = sb + a_lane, bl = sb + b_lane;

        // ks=0 fragments
#pragma unroll
        for (int mt = 0; mt < 4; ++mt)
            ldm_x4(a_buf[0][mt], al + (uint32_t)(mt * 16 * SA_BYTES));
#pragma unroll
        for (int nt = 0; nt < 4; ++nt)
            ldm_x4(b_buf[0][nt], bl + (uint32_t)(nt * 16 * SA_BYTES));

#pragma unroll
        for (int ks = 0; ks < 4; ++ks) {
            int cur = ks & 1, nxt = cur ^ 1;
            if (ks < 3) {
#pragma unroll
                for (int mt = 0; mt < 4; ++mt)
                    ldm_x4(a_buf[nxt][mt],
                           al + (uint32_t)(mt * 16 * SA_BYTES + (ks + 1) * 32));
#pragma unroll
                for (int nt = 0; nt < 4; ++nt)
                    ldm_x4(b_buf[nxt][nt],
                           bl + (uint32_t)(nt * 16 * SA_BYTES + (ks + 1) * 32));
            }
#pragma unroll
            for (int mt = 0; mt < 4; ++mt)
#pragma unroll
                for (int nt = 0; nt < 8; ++nt)
                    mma_bf16(acc[mt][nt], a_buf[cur][mt], &b_buf[cur][nt >> 1][(nt & 1) * 2]);
        }
    }

    // Epilogue: fused norms; lane l owns rows q, q+8 and col pair 2*(l%4).
    const int q = lid >> 2, rr = lid & 3;
#pragma unroll
    for (int mt = 0; mt < 4; ++mt) {
        int r0 = mw + mt * 16 + q;
        float x2a = s_x2[r0], x2b = s_x2[r0 + 8];
        float* orow0 = out + (size_t)(m0 + r0) * N;
        float* orow1 = orow0 + (size_t)8 * N;
#pragma unroll
        for (int nt = 0; nt < 8; ++nt) {
            int cl = nw + nt * 8 + 2 * rr;      // local col (even)
            int col = n0 + cl;
            if (col < N) {
                float w2a = s_w2[cl], w2b = s_w2[cl + 1];
                float2 v0, v1;
                v0.x = (2.0f * INV_F) * acc[mt][nt][0] - (x2a + w2a) * INV_F;
                v0.y = (2.0f * INV_F) * acc[mt][nt][1] - (x2a + w2b) * INV_F;
                v1.x = (2.0f * INV_F) * acc[mt][nt][2] - (x2b + w2a) * INV_F;
                v1.y = (2.0f * INV_F) * acc[mt][nt][3] - (x2b + w2b) * INV_F;
                *reinterpret_cast<float2*>(orow0 + col) = v0;
                *reinterpret_cast<float2*>(orow1 + col) = v1;
            }
        }
    }
}

extern "C" void kernel_launch(void* const* d_in, const int* in_sizes, int n_in,
                              void* d_out, int out_size) {
    const float* x = (const float*)d_in[0];
    const float* w = (const float*)d_in[1];
    float* out = (float*)d_out;
    int M = in_sizes[0] / K_DIM;   // 16384
    int N = in_sizes[1] / K_DIM;   // 1000

    convert_kernel<<<M + N_PAD, 256>>>(x, w, M, N);

    cudaFuncSetAttribute(gemm_mma_kernel,
                         cudaFuncAttributeMaxDynamicSharedMemorySize, DYN_SMEM);
    gemm_mma_kernel<<<dim3(N_PAD / BN, M / BM), 128, DYN_SMEM>>>(out, N);
}

// round 9
// speedup vs baseline: 1.1015x; 1.1015x over previous
#include <cuda_runtime.h>
#include <cuda_bf16.h>
#include <cstdint>

#define K_DIM 2048
#define INV_F (1.0f / 2048.0f)
#define M_TOTAL 16384
#define N_PAD 1024
#define BM 128
#define BN 128
#define BK 64                               // bf16 per stage (128 bytes/row)
#define STAGES 3
#define SA_BYTES 144                        // 128B data + 16B pad: conflict-free
#define TILE_BYTES (128 * SA_BYTES)         // 18432 per operand tile
#define STAGE_BYTES (2 * TILE_BYTES)        // 36864
#define DYN_SMEM (STAGES * STAGE_BYTES)     // 110592 (2 CTAs/SM)

// Scratch (no device allocation allowed): bf16 operands + exact fp32 norms.
__device__ __align__(16) __nv_bfloat16 g_xb[(size_t)M_TOTAL * K_DIM];
__device__ __align__(16) __nv_bfloat16 g_wb[(size_t)N_PAD * K_DIM];
__device__ float g_x2[M_TOTAL];
__device__ float g_w2[N_PAD];

__device__ __forceinline__ uint32_t smem_u32(const void* p) {
    return (uint32_t)__cvta_generic_to_shared(p);
}

__device__ __forceinline__ void ldm_x4(uint32_t* r, uint32_t addr) {
    asm volatile("ldmatrix.sync.aligned.m8n8.x4.shared.b16 {%0,%1,%2,%3}, [%4];"
                 : "=r"(r[0]), "=r"(r[1]), "=r"(r[2]), "=r"(r[3]) : "r"(addr));
}

__device__ __forceinline__ void mma_bf16(float* d, const uint32_t* a, const uint32_t* b) {
    asm volatile(
        "mma.sync.aligned.m16n8k16.row.col.f32.bf16.bf16.f32 "
        "{%0,%1,%2,%3}, {%4,%5,%6,%7}, {%8,%9}, {%0,%1,%2,%3};"
        : "+f"(d[0]), "+f"(d[1]), "+f"(d[2]), "+f"(d[3])
        : "r"(a[0]), "r"(a[1]), "r"(a[2]), "r"(a[3]), "r"(b[0]), "r"(b[1]));
}

// ---------------- fused fp32->bf16 convert + exact fp32 row sum-of-squares ----------------

__global__ void __launch_bounds__(256) convert_kernel(const float* __restrict__ x,
                                                      const float* __restrict__ w,
                                                      int M, int N) {
    int b = blockIdx.x;
    const float4* src;
    uint2* dst;
    float* norm;
    if (b < M) {
        src = reinterpret_cast<const float4*>(x + (size_t)b * K_DIM);
        dst = reinterpret_cast<uint2*>(g_xb + (size_t)b * K_DIM);
        norm = &g_x2[b];
    } else {
        int row = b - M;
        dst = reinterpret_cast<uint2*>(g_wb + (size_t)row * K_DIM);
        if (row >= N) {
#pragma unroll
            for (int i = 0; i < 2; ++i) dst[threadIdx.x + i * 256] = make_uint2(0u, 0u);
            if (threadIdx.x == 0) g_w2[row] = 0.f;
            return;
        }
        src = reinterpret_cast<const float4*>(w + (size_t)row * K_DIM);
        norm = &g_w2[row];
    }
    float s = 0.f;
#pragma unroll
    for (int i = 0; i < 2; ++i) {
        int idx = threadIdx.x + i * 256;
        float4 v = src[idx];
        s += v.x * v.x + v.y * v.y + v.z * v.z + v.w * v.w;
        __nv_bfloat162 p0 = __float22bfloat162_rn(make_float2(v.x, v.y));
        __nv_bfloat162 p1 = __float22bfloat162_rn(make_float2(v.z, v.w));
        uint2 o;
        o.x = *reinterpret_cast<uint32_t*>(&p0);
        o.y = *reinterpret_cast<uint32_t*>(&p1);
        dst[idx] = o;
    }
#pragma unroll
    for (int o = 16; o > 0; o >>= 1) s += __shfl_xor_sync(0xffffffffu, s, o);
    __shared__ float red[8];
    if ((threadIdx.x & 31) == 0) red[threadIdx.x >> 5] = s;
    __syncthreads();
    if (threadIdx.x == 0) {
        float t = 0.f;
#pragma unroll
        for (int i = 0; i < 8; ++i) t += red[i];
        *norm = t;
    }
}

// ---------------- bf16 mma.sync GEMM, CTA 128x128, 8 warps of 64x32 ----------------
// out[m,n] = -(x2[m] - 2*sum_k X[m,k]W[n,k] + w2[n]) / F

__device__ __forceinline__ void load_stage(uint32_t base, int s, int kt,
                                           int m0, int n0, int tid) {
    uint32_t sb = base + (uint32_t)s * STAGE_BYTES;
    const __nv_bfloat16* xa = g_xb + (size_t)m0 * K_DIM + kt * BK;
    const __nv_bfloat16* wb = g_wb + (size_t)n0 * K_DIM + kt * BK;
#pragma unroll
    for (int i = 0; i < 8; ++i) {
        int idx = tid + i * 256;                 // 0..2047
        int op = idx >> 10;                      // 0 = A, 1 = B
        int r = (idx >> 3) & 127;
        int c = idx & 7;
        uint32_t dst = sb + (uint32_t)op * TILE_BYTES + (uint32_t)(r * SA_BYTES + c * 16);
        const __nv_bfloat16* src = (op ? wb : xa) + (size_t)r * K_DIM + c * 8;
        asm volatile("cp.async.cg.shared.global [%0], [%1], 16;"
                     :: "r"(dst), "l"(src) : "memory");
    }
    asm volatile("cp.async.commit_group;" ::: "memory");
}

__global__ void __launch_bounds__(256, 2) gemm_mma_kernel(float* __restrict__ out, int N) {
    extern __shared__ __align__(16) char dyn_smem[];
    __shared__ float s_x2[BM];
    __shared__ float s_w2[BN];

    const uint32_t base = smem_u32(dyn_smem);
    const int tid = threadIdx.x;
    const int wid = tid >> 5, lid = tid & 31;
    const int m0 = blockIdx.y * BM;
    const int n0 = blockIdx.x * BN;
    const int mw = (wid >> 2) * 64;    // warp M offset
    const int nw = (wid & 3) * 32;     // warp N offset

    if (tid < BM) s_x2[tid] = g_x2[m0 + tid];
    else          s_w2[tid - BM] = g_w2[n0 + tid - BM];

    // Prologue: prefetch STAGES-1 stages.
#pragma unroll
    for (int s = 0; s < STAGES - 1; ++s) load_stage(base, s, s, m0, n0, tid);

    float acc[4][4][4] = {};

    const uint32_t a_lane = (uint32_t)((mw + (lid & 15)) * SA_BYTES + (lid >> 4) * 16);
    const uint32_t b_lane = (uint32_t)TILE_BYTES +
        (uint32_t)((nw + (lid & 7) + ((lid >> 4) << 3)) * SA_BYTES + ((lid >> 3) & 1) * 16);

    const int NITER = K_DIM / BK;  // 32
    for (int kt = 0; kt < NITER; ++kt) {
        asm volatile("cp.async.wait_group %0;" :: "n"(STAGES - 2) : "memory");
        __syncthreads();

        // Hoist next-stage gmem prefetch so L2 latency overlaps this kt's compute.
        int kl = kt + STAGES - 1;
        if (kl < NITER) load_stage(base, kl % STAGES, kl, m0, n0, tid);
        else asm volatile("cp.async.commit_group;" ::: "memory");

        uint32_t sb = base + (uint32_t)(kt % STAGES) * STAGE_BYTES;
        const uint32_t al = sb + a_lane, bl = sb + b_lane;

        // B fragments double-buffered across ks (fits the 128-reg cap; A reloads per ks).
        uint32_t b_buf[2][2][4];
#pragma unroll
        for (int nt = 0; nt < 2; ++nt)
            ldm_x4(b_buf[0][nt], bl + (uint32_t)(nt * 16 * SA_BYTES));

#pragma unroll
        for (int ks = 0; ks < 4; ++ks) {
            int cur = ks & 1, nxt = cur ^ 1;
            if (ks < 3) {
#pragma unroll
                for (int nt = 0; nt < 2; ++nt)
                    ldm_x4(b_buf[nxt][nt],
                           bl + (uint32_t)(nt * 16 * SA_BYTES + (ks + 1) * 32));
            }
            uint32_t a_frag[4][4];
#pragma unroll
            for (int mt = 0; mt < 4; ++mt)
                ldm_x4(a_frag[mt], al + (uint32_t)(mt * 16 * SA_BYTES + ks * 32));
#pragma unroll
            for (int mt = 0; mt < 4; ++mt)
#pragma unroll
                for (int nt = 0; nt < 4; ++nt)
                    mma_bf16(acc[mt][nt], a_frag[mt], &b_buf[cur][nt >> 1][(nt & 1) * 2]);
        }
    }

    // Epilogue: fused norms; lane l owns rows q, q+8 and col pair 2*(l%4).
    const int q = lid >> 2, rr = lid & 3;
#pragma unroll
    for (int mt = 0; mt < 4; ++mt) {
        int r0 = mw + mt * 16 + q;
        float x2a = s_x2[r0], x2b = s_x2[r0 + 8];
        float* orow0 = out + (size_t)(m0 + r0) * N;
        float* orow1 = orow0 + (size_t)8 * N;
#pragma unroll
        for (int nt = 0; nt < 4; ++nt) {
            int cl = nw + nt * 8 + 2 * rr;      // local col (even)
            int col = n0 + cl;
            if (col < N) {
                float w2a = s_w2[cl], w2b = s_w2[cl + 1];
                float2 v0, v1;
                v0.x = (2.0f * INV_F) * acc[mt][nt][0] - (x2a + w2a) * INV_F;
                v0.y = (2.0f * INV_F) * acc[mt][nt][1] - (x2a + w2b) * INV_F;
                v1.x = (2.0f * INV_F) * acc[mt][nt][2] - (x2b + w2a) * INV_F;
                v1.y = (2.0f * INV_F) * acc[mt][nt][3] - (x2b + w2b) * INV_F;
                *reinterpret_cast<float2*>(orow0 + col) = v0;
                *reinterpret_cast<float2*>(orow1 + col) = v1;
            }
        }
    }
}

extern "C" void kernel_launch(void* const* d_in, const int* in_sizes, int n_in,
                              void* d_out, int out_size) {
    const float* x = (const float*)d_in[0];
    const float* w = (const float*)d_in[1];
    float* out = (float*)d_out;
    int M = in_sizes[0] / K_DIM;   // 16384
    int N = in_sizes[1] / K_DIM;   // 1000

    convert_kernel<<<M + N_PAD, 256>>>(x, w, M, N);

    cudaFuncSetAttribute(gemm_mma_kernel,
                         cudaFuncAttributeMaxDynamicSharedMemorySize, DYN_SMEM);
    gemm_mma_kernel<<<dim3(N_PAD / BN, M / BM), 256, DYN_SMEM>>>(out, N);
}

// round 10
// speedup vs baseline: 1.1908x; 1.0810x over previous
#include <cuda_runtime.h>
#include <cuda_bf16.h>
#include <cstdint>

#define K_DIM 2048
#define INV_F (1.0f / 2048.0f)
#define M_TOTAL 16384
#define N_PAD 1024
#define BM 128
#define BN 128
#define BK 64                               // bf16 per stage (128 bytes/row)
#define STAGES 3
#define SA_BYTES 144                        // 128B data + 16B pad: conflict-free
#define TILE_BYTES (128 * SA_BYTES)         // 18432 per operand tile
#define STAGE_BYTES (2 * TILE_BYTES)        // 36864
#define DYN_SMEM (STAGES * STAGE_BYTES)     // 110592 (2 CTAs/SM)

// Scratch (no device allocation allowed): bf16 operands + exact fp32 norms.
__device__ __align__(16) __nv_bfloat16 g_xb[(size_t)M_TOTAL * K_DIM];
__device__ __align__(16) __nv_bfloat16 g_wb[(size_t)N_PAD * K_DIM];
__device__ float g_x2[M_TOTAL];
__device__ float g_w2[N_PAD];

__device__ __forceinline__ uint32_t smem_u32(const void* p) {
    return (uint32_t)__cvta_generic_to_shared(p);
}

__device__ __forceinline__ void ldm_x4(uint32_t* r, uint32_t addr) {
    asm volatile("ldmatrix.sync.aligned.m8n8.x4.shared.b16 {%0,%1,%2,%3}, [%4];"
                 : "=r"(r[0]), "=r"(r[1]), "=r"(r[2]), "=r"(r[3]) : "r"(addr));
}

__device__ __forceinline__ void mma_bf16(float* d, const uint32_t* a, const uint32_t* b) {
    asm volatile(
        "mma.sync.aligned.m16n8k16.row.col.f32.bf16.bf16.f32 "
        "{%0,%1,%2,%3}, {%4,%5,%6,%7}, {%8,%9}, {%0,%1,%2,%3};"
        : "+f"(d[0]), "+f"(d[1]), "+f"(d[2]), "+f"(d[3])
        : "r"(a[0]), "r"(a[1]), "r"(a[2]), "r"(a[3]), "r"(b[0]), "r"(b[1]));
}

// ---------------- fused fp32->bf16 convert + exact fp32 row sum-of-squares ----------------
// One block per row. 256 threads x 8 contiguous elems = 2048. Single 16B store/thread.
// Blocks [0, M): x rows.  Blocks [M, M+N_PAD): w rows (zero-padded past N).

__global__ void __launch_bounds__(256) convert_kernel(const float* __restrict__ x,
                                                      const float* __restrict__ w,
                                                      int M, int N) {
    int b = blockIdx.x;
    const float4* src;
    uint4* dst;
    float* norm;
    if (b < M) {
        src = reinterpret_cast<const float4*>(x + (size_t)b * K_DIM);
        dst = reinterpret_cast<uint4*>(g_xb + (size_t)b * K_DIM);
        norm = &g_x2[b];
    } else {
        int row = b - M;
        dst = reinterpret_cast<uint4*>(g_wb + (size_t)row * K_DIM);
        if (row >= N) {
            dst[threadIdx.x] = make_uint4(0u, 0u, 0u, 0u);
            if (threadIdx.x == 0) g_w2[row] = 0.f;
            return;
        }
        src = reinterpret_cast<const float4*>(w + (size_t)row * K_DIM);
        norm = &g_w2[row];
    }
    float4 v0 = src[threadIdx.x * 2];
    float4 v1 = src[threadIdx.x * 2 + 1];
    float s = v0.x * v0.x + v0.y * v0.y + v0.z * v0.z + v0.w * v0.w +
              v1.x * v1.x + v1.y * v1.y + v1.z * v1.z + v1.w * v1.w;
    __nv_bfloat162 p0 = __float22bfloat162_rn(make_float2(v0.x, v0.y));
    __nv_bfloat162 p1 = __float22bfloat162_rn(make_float2(v0.z, v0.w));
    __nv_bfloat162 p2 = __float22bfloat162_rn(make_float2(v1.x, v1.y));
    __nv_bfloat162 p3 = __float22bfloat162_rn(make_float2(v1.z, v1.w));
    uint4 o;
    o.x = *reinterpret_cast<uint32_t*>(&p0);
    o.y = *reinterpret_cast<uint32_t*>(&p1);
    o.z = *reinterpret_cast<uint32_t*>(&p2);
    o.w = *reinterpret_cast<uint32_t*>(&p3);
    dst[threadIdx.x] = o;

#pragma unroll
    for (int o2 = 16; o2 > 0; o2 >>= 1) s += __shfl_xor_sync(0xffffffffu, s, o2);
    __shared__ float red[8];
    if ((threadIdx.x & 31) == 0) red[threadIdx.x >> 5] = s;
    __syncthreads();
    if (threadIdx.x == 0) {
        float t = 0.f;
#pragma unroll
        for (int i = 0; i < 8; ++i) t += red[i];
        *norm = t;
    }
}

// ---------------- bf16 mma.sync GEMM, CTA 128x128, 8 warps of 64x32 (R5 layout) ----------------
// out[m,n] = -(x2[m] - 2*sum_k X[m,k]W[n,k] + w2[n]) / F

__device__ __forceinline__ void load_stage(uint32_t base, int s, int kt,
                                           int m0, int n0, int tid) {
    uint32_t sb = base + (uint32_t)s * STAGE_BYTES;
    const __nv_bfloat16* xa = g_xb + (size_t)m0 * K_DIM + kt * BK;
    const __nv_bfloat16* wb = g_wb + (size_t)n0 * K_DIM + kt * BK;
#pragma unroll
    for (int i = 0; i < 8; ++i) {
        int idx = tid + i * 256;                 // 0..2047
        int op = idx >> 10;                      // 0 = A, 1 = B
        int r = (idx >> 3) & 127;
        int c = idx & 7;
        uint32_t dst = sb + (uint32_t)op * TILE_BYTES + (uint32_t)(r * SA_BYTES + c * 16);
        const __nv_bfloat16* src = (op ? wb : xa) + (size_t)r * K_DIM + c * 8;
        asm volatile("cp.async.cg.shared.global [%0], [%1], 16;"
                     :: "r"(dst), "l"(src) : "memory");
    }
    asm volatile("cp.async.commit_group;" ::: "memory");
}

__global__ void __launch_bounds__(256, 2) gemm_mma_kernel(float* __restrict__ out, int N) {
    extern __shared__ __align__(16) char dyn_smem[];
    __shared__ float s_x2[BM];
    __shared__ float s_w2[BN];

    const uint32_t base = smem_u32(dyn_smem);
    const int tid = threadIdx.x;
    const int wid = tid >> 5, lid = tid & 31;
    const int m0 = blockIdx.y * BM;
    const int n0 = blockIdx.x * BN;
    const int mw = (wid >> 2) * 64;    // warp M offset
    const int nw = (wid & 3) * 32;     // warp N offset

    if (tid < BM) s_x2[tid] = g_x2[m0 + tid];
    else          s_w2[tid - BM] = g_w2[n0 + tid - BM];

    // Prologue: prefetch STAGES-1 stages.
#pragma unroll
    for (int s = 0; s < STAGES - 1; ++s) load_stage(base, s, s, m0, n0, tid);

    float acc[4][4][4] = {};

    const uint32_t a_lane = (uint32_t)((mw + (lid & 15)) * SA_BYTES + (lid >> 4) * 16);
    const uint32_t b_lane = (uint32_t)TILE_BYTES +
        (uint32_t)((nw + (lid & 7) + ((lid >> 4) << 3)) * SA_BYTES + ((lid >> 3) & 1) * 16);

    const int NITER = K_DIM / BK;  // 32
    for (int kt = 0; kt < NITER; ++kt) {
        asm volatile("cp.async.wait_group %0;" :: "n"(STAGES - 2) : "memory");
        __syncthreads();
        uint32_t sb = base + (uint32_t)(kt % STAGES) * STAGE_BYTES;

#pragma unroll
        for (int ks = 0; ks < 4; ++ks) {          // 4 x k16 within the 128B rows
            uint32_t a_frag[4][4], b_frag[2][4];
#pragma unroll
            for (int mt = 0; mt < 4; ++mt)
                ldm_x4(a_frag[mt], sb + a_lane + (uint32_t)(mt * 16 * SA_BYTES + ks * 32));
#pragma unroll
            for (int nt = 0; nt < 2; ++nt)
                ldm_x4(b_frag[nt], sb + b_lane + (uint32_t)(nt * 16 * SA_BYTES + ks * 32));
#pragma unroll
            for (int mt = 0; mt < 4; ++mt)
#pragma unroll
                for (int nt = 0; nt < 4; ++nt)
                    mma_bf16(acc[mt][nt], a_frag[mt], &b_frag[nt >> 1][(nt & 1) * 2]);
        }

        int kl = kt + STAGES - 1;
        if (kl < NITER) load_stage(base, kl % STAGES, kl, m0, n0, tid);
        else asm volatile("cp.async.commit_group;" ::: "memory");
    }

    // Epilogue: fused norms; lane l owns rows q, q+8 and col pair 2*(l%4).
    const int q = lid >> 2, rr = lid & 3;
#pragma unroll
    for (int mt = 0; mt < 4; ++mt) {
        int r0 = mw + mt * 16 + q;
        float x2a = s_x2[r0], x2b = s_x2[r0 + 8];
        float* orow0 = out + (size_t)(m0 + r0) * N;
        float* orow1 = orow0 + (size_t)8 * N;
#pragma unroll
        for (int nt = 0; nt < 4; ++nt) {
            int cl = nw + nt * 8 + 2 * rr;      // local col (even)
            int col = n0 + cl;
            if (col < N) {
                float w2a = s_w2[cl], w2b = s_w2[cl + 1];
                float2 v0, v1;
                v0.x = (2.0f * INV_F) * acc[mt][nt][0] - (x2a + w2a) * INV_F;
                v0.y = (2.0f * INV_F) * acc[mt][nt][1] - (x2a + w2b) * INV_F;
                v1.x = (2.0f * INV_F) * acc[mt][nt][2] - (x2b + w2a) * INV_F;
                v1.y = (2.0f * INV_F) * acc[mt][nt][3] - (x2b + w2b) * INV_F;
                *reinterpret_cast<float2*>(orow0 + col) = v0;
                *reinterpret_cast<float2*>(orow1 + col) = v1;
            }
        }
    }
}

extern "C" void kernel_launch(void* const* d_in, const int* in_sizes, int n_in,
                              void* d_out, int out_size) {
    const float* x = (const float*)d_in[0];
    const float* w = (const float*)d_in[1];
    float* out = (float*)d_out;
    int M = in_sizes[0] / K_DIM;   // 16384
    int N = in_sizes[1] / K_DIM;   // 1000

    convert_kernel<<<M + N_PAD, 256>>>(x, w, M, N);

    cudaFuncSetAttribute(gemm_mma_kernel,
                         cudaFuncAttributeMaxDynamicSharedMemorySize, DYN_SMEM);
    gemm_mma_kernel<<<dim3(N_PAD / BN, M / BM), 256, DYN_SMEM>>>(out, N);
}